// round 1
// baseline (speedup 1.0000x reference)
#include <cuda_runtime.h>
#include <cstdint>

// Problem constants
#define BB 32
#define CC 256
#define HH 56
#define WW 56
#define NN 1024
#define KK (HH * WW)      // 3136
#define MM (BB * CC)      // 8192

// GEMM tiling
#define TK 16
#define TM 128
#define TN 128

// Scratch: y[b*C+c, n] (32 MB) and transposed W_d [c][n] (1 MB)
__device__ float g_y[(size_t)MM * NN];
__device__ float g_wdt[(size_t)CC * NN];

__device__ __forceinline__ unsigned long long pack2(float x) {
    unsigned long long r;
    asm("mov.b64 %0, {%1, %1};" : "=l"(r) : "f"(x));
    return r;
}

__device__ __forceinline__ float2 unpack2(unsigned long long v) {
    float2 r;
    asm("mov.b64 {%0, %1}, %2;" : "=f"(r.x), "=f"(r.y) : "l"(v));
    return r;
}

#define FMA2(d, a, b) asm("fma.rn.f32x2 %0, %1, %2, %0;" : "+l"(d) : "l"(a), "l"(b))

// C[m, n] = sum_k A[m, k] * B[n, k]
// A = x viewed as (8192, 3136) row-major; B = W_s (1024, 3136) row-major.
__global__ void __launch_bounds__(256, 2)
gemm_f32x2(const float* __restrict__ A, const float* __restrict__ Bm) {
    __shared__ __align__(16) float As[2][TK][TM];
    __shared__ __align__(16) float Bs[2][TK][TN];

    const int tid = threadIdx.x;
    const int tx = tid & 15;      // n micro-tile
    const int ty = tid >> 4;      // m micro-tile
    const int m0 = blockIdx.y * TM;
    const int n0 = blockIdx.x * TN;

    // Global load mapping: 4 lanes per row (64B contiguous), 64 rows per pass.
    const int lrow = tid >> 2;           // 0..63
    const int lk   = (tid & 3) * 4;      // 0,4,8,12

    const float* Ag = A  + (size_t)(m0 + lrow) * KK + lk;
    const float* Bg = Bm + (size_t)(n0 + lrow) * KK + lk;

    // 4 m-pairs x 8 n columns of packed f32x2 accumulators (covers 8x8 floats)
    unsigned long long acc[4][8];
#pragma unroll
    for (int i = 0; i < 4; i++)
#pragma unroll
        for (int j = 0; j < 8; j++) acc[i][j] = 0ull;

    // ---- prologue: load tile 0 ----
    float4 ra0 = *(const float4*)(Ag);
    float4 ra1 = *(const float4*)(Ag + (size_t)64 * KK);
    float4 rb0 = *(const float4*)(Bg);
    float4 rb1 = *(const float4*)(Bg + (size_t)64 * KK);

    As[0][lk + 0][lrow] = ra0.x; As[0][lk + 1][lrow] = ra0.y;
    As[0][lk + 2][lrow] = ra0.z; As[0][lk + 3][lrow] = ra0.w;
    As[0][lk + 0][lrow + 64] = ra1.x; As[0][lk + 1][lrow + 64] = ra1.y;
    As[0][lk + 2][lrow + 64] = ra1.z; As[0][lk + 3][lrow + 64] = ra1.w;
    Bs[0][lk + 0][lrow] = rb0.x; Bs[0][lk + 1][lrow] = rb0.y;
    Bs[0][lk + 2][lrow] = rb0.z; Bs[0][lk + 3][lrow] = rb0.w;
    Bs[0][lk + 0][lrow + 64] = rb1.x; Bs[0][lk + 1][lrow + 64] = rb1.y;
    Bs[0][lk + 2][lrow + 64] = rb1.z; Bs[0][lk + 3][lrow + 64] = rb1.w;
    __syncthreads();

    const int NK = KK / TK;  // 196
    int buf = 0;

#pragma unroll 1
    for (int kt = 1; kt <= NK; kt++) {
        if (kt < NK) {
            const float* Agk = Ag + kt * TK;
            const float* Bgk = Bg + kt * TK;
            ra0 = *(const float4*)(Agk);
            ra1 = *(const float4*)(Agk + (size_t)64 * KK);
            rb0 = *(const float4*)(Bgk);
            rb1 = *(const float4*)(Bgk + (size_t)64 * KK);
        }

#pragma unroll
        for (int kk = 0; kk < TK; kk++) {
            // A pairs: consecutive m in SMEM -> direct 64-bit packed loads
            const ulonglong2* ap = (const ulonglong2*)&As[buf][kk][ty * 8];
            ulonglong2 apl = ap[0];
            ulonglong2 aph = ap[1];
            unsigned long long a2[4] = {apl.x, apl.y, aph.x, aph.y};

            float4 b0 = *(const float4*)&Bs[buf][kk][tx * 8];
            float4 b1 = *(const float4*)&Bs[buf][kk][tx * 8 + 4];
            unsigned long long bd[8] = {
                pack2(b0.x), pack2(b0.y), pack2(b0.z), pack2(b0.w),
                pack2(b1.x), pack2(b1.y), pack2(b1.z), pack2(b1.w)};

#pragma unroll
            for (int i = 0; i < 4; i++)
#pragma unroll
                for (int j = 0; j < 8; j++) FMA2(acc[i][j], a2[i], bd[j]);
        }

        if (kt < NK) {
            int nb = buf ^ 1;
            As[nb][lk + 0][lrow] = ra0.x; As[nb][lk + 1][lrow] = ra0.y;
            As[nb][lk + 2][lrow] = ra0.z; As[nb][lk + 3][lrow] = ra0.w;
            As[nb][lk + 0][lrow + 64] = ra1.x; As[nb][lk + 1][lrow + 64] = ra1.y;
            As[nb][lk + 2][lrow + 64] = ra1.z; As[nb][lk + 3][lrow + 64] = ra1.w;
            Bs[nb][lk + 0][lrow] = rb0.x; Bs[nb][lk + 1][lrow] = rb0.y;
            Bs[nb][lk + 2][lrow] = rb0.z; Bs[nb][lk + 3][lrow] = rb0.w;
            Bs[nb][lk + 0][lrow + 64] = rb1.x; Bs[nb][lk + 1][lrow + 64] = rb1.y;
            Bs[nb][lk + 2][lrow + 64] = rb1.z; Bs[nb][lk + 3][lrow + 64] = rb1.w;
            __syncthreads();
            buf = nb;
        }
    }

    // ---- epilogue: unpack and store to scratch y ----
    float* Cp = g_y + (size_t)(m0 + ty * 8) * NN + n0 + tx * 8;
#pragma unroll
    for (int i = 0; i < 4; i++) {
        float2 p[8];
#pragma unroll
        for (int j = 0; j < 8; j++) p[j] = unpack2(acc[i][j]);
        float4 lo0 = {p[0].x, p[1].x, p[2].x, p[3].x};
        float4 lo1 = {p[4].x, p[5].x, p[6].x, p[7].x};
        float4 hi0 = {p[0].y, p[1].y, p[2].y, p[3].y};
        float4 hi1 = {p[4].y, p[5].y, p[6].y, p[7].y};
        float* r0 = Cp + (size_t)(2 * i) * NN;
        float* r1 = Cp + (size_t)(2 * i + 1) * NN;
        *(float4*)(r0) = lo0;
        *(float4*)(r0 + 4) = lo1;
        *(float4*)(r1) = hi0;
        *(float4*)(r1 + 4) = hi1;
    }
}

// g_wdt[c][n] = W_d[n][c] (coalesced writes)
__global__ void __launch_bounds__(256)
transpose_wd(const float* __restrict__ Wd) {
    int idx = blockIdx.x * 256 + threadIdx.x;   // over 262144
    int c = idx >> 10;
    int n = idx & 1023;
    g_wdt[idx] = Wd[(size_t)n * CC + c];
}

// out[b, n] = sum_c y[b*C+c, n] * wdt[c, n] + Wb[n]
__global__ void __launch_bounds__(256)
reduce_k(const float* __restrict__ Wb, float* __restrict__ out) {
    int idx = blockIdx.x * 256 + threadIdx.x;   // over 32768
    int b = idx >> 10;
    int n = idx & 1023;
    const float* y = g_y + ((size_t)b * CC) * NN + n;
    float s = 0.f;
#pragma unroll 8
    for (int c = 0; c < CC; c++)
        s = fmaf(y[(size_t)c * NN], g_wdt[(size_t)c * NN + n], s);
    out[idx] = s + Wb[n];
}

extern "C" void kernel_launch(void* const* d_in, const int* in_sizes, int n_in,
                              void* d_out, int out_size) {
    const float* x  = (const float*)d_in[0];   // (B, C, H, W)
    const float* Ws = (const float*)d_in[1];   // (N, H, W)
    const float* Wd = (const float*)d_in[2];   // (N, C, 1, 1)
    const float* Wb = (const float*)d_in[3];   // (1, N)
    float* out = (float*)d_out;                // (B, N)

    dim3 ggrid(NN / TN, MM / TM);              // (8, 64)
    gemm_f32x2<<<ggrid, 256>>>(x, Ws);
    transpose_wd<<<(CC * NN) / 256, 256>>>(Wd);
    reduce_k<<<(BB * NN) / 256, 256>>>(Wb, out);
}

// round 4
// speedup vs baseline: 2.6093x; 2.6093x over previous
#include <cuda_runtime.h>
#include <cuda_bf16.h>
#include <cstdint>

// Problem constants
#define BB 32
#define CC 256
#define NNV 1024
#define KK 3136
#define MM (BB * CC)        // 8192
#define K2 (2 * KK)         // 6272 (hi | lo)

// GEMM tiling (sm80-style HMMA; nothing arch-suffixed -> compiles at sm_103)
#define BM 128
#define BN 128
#define BK 32
#define KSEG 98             // 3136/32 chunks per segment
#define NCHUNK (3 * KSEG)   // 294: segments (Ah,Bh), (Al,Bh), (Ah,Bl)

// Scratch (device globals: no allocation allowed)
__device__ __nv_bfloat16 g_A2[(size_t)MM * K2];    // x split  [hi | lo]
__device__ __nv_bfloat16 g_B2[(size_t)NNV * K2];   // Ws split [hi | lo]
__device__ float g_y[(size_t)MM * NNV];
__device__ float g_wdt[(size_t)CC * NNV];

__device__ __forceinline__ uint32_t smem_u32(const void* p) {
    uint32_t a;
    asm("{ .reg .u64 t; cvta.to.shared.u64 t, %1; cvt.u32.u64 %0, t; }" : "=r"(a) : "l"(p));
    return a;
}
#define CP16(dst, src)  asm volatile("cp.async.cg.shared.global [%0], [%1], 16;" :: "r"(dst), "l"(src) : "memory")
#define CP_COMMIT()     asm volatile("cp.async.commit_group;" ::: "memory")
#define CP_WAIT1()      asm volatile("cp.async.wait_group 1;" ::: "memory")
#define CP_WAIT0()      asm volatile("cp.async.wait_group 0;" ::: "memory")

#define LDSM_X4(r0, r1, r2, r3, a) \
    asm volatile("ldmatrix.sync.aligned.m8n8.x4.shared.b16 {%0,%1,%2,%3}, [%4];" \
        : "=r"(r0), "=r"(r1), "=r"(r2), "=r"(r3) : "r"(a))

#define MMA16816(d, a, b) \
    asm volatile("mma.sync.aligned.m16n8k16.row.col.f32.bf16.bf16.f32 " \
        "{%0,%1,%2,%3}, {%4,%5,%6,%7}, {%8,%9}, {%0,%1,%2,%3};" \
        : "+f"((d)[0]), "+f"((d)[1]), "+f"((d)[2]), "+f"((d)[3]) \
        : "r"((a)[0]), "r"((a)[1]), "r"((a)[2]), "r"((a)[3]), "r"((b)[0]), "r"((b)[1]))

// Row = 32 bf16 = 64B = 4x16B units; swizzle u^((row>>1)&3) -> ldmatrix conflict-free
__device__ __forceinline__ uint32_t swz(int row, int u) {
    return (uint32_t)(row * 64 + ((u ^ ((row >> 1) & 3)) << 4));
}

// ---------------- split-to-bf16 conversion ----------------
__device__ __forceinline__ void split4(float4 v, uint2& hp, uint2& lp) {
    float a[4] = {v.x, v.y, v.z, v.w};
    uint32_t h[4], l[4];
#pragma unroll
    for (int i = 0; i < 4; i++) {
        __nv_bfloat16 hb = __float2bfloat16(a[i]);
        float res = a[i] - __bfloat162float(hb);
        __nv_bfloat16 lb = __float2bfloat16(res);
        h[i] = __bfloat16_as_ushort(hb);
        l[i] = __bfloat16_as_ushort(lb);
    }
    hp.x = h[0] | (h[1] << 16); hp.y = h[2] | (h[3] << 16);
    lp.x = l[0] | (l[1] << 16); lp.y = l[2] | (l[3] << 16);
}

__global__ void __launch_bounds__(256) split_x(const float* __restrict__ src) {
    size_t i = (size_t)blockIdx.x * 256 + threadIdx.x;
    size_t r = i / (KK / 4); int k4 = (int)(i % (KK / 4));
    float4 v = ((const float4*)src)[i];
    uint2 hp, lp; split4(v, hp, lp);
    __nv_bfloat16* row = g_A2 + r * K2;
    *(uint2*)(row + (size_t)k4 * 4)      = hp;
    *(uint2*)(row + KK + (size_t)k4 * 4) = lp;
}

__global__ void __launch_bounds__(256) split_w(const float* __restrict__ src) {
    size_t i = (size_t)blockIdx.x * 256 + threadIdx.x;
    size_t r = i / (KK / 4); int k4 = (int)(i % (KK / 4));
    float4 v = ((const float4*)src)[i];
    uint2 hp, lp; split4(v, hp, lp);
    __nv_bfloat16* row = g_B2 + r * K2;
    *(uint2*)(row + (size_t)k4 * 4)      = hp;
    *(uint2*)(row + KK + (size_t)k4 * 4) = lp;
}

// ---------------- HMMA GEMM: y = A2 x B2^T over 3 split segments ----------------
__global__ void __launch_bounds__(256, 2) gemm_hmma() {
    __shared__ __align__(128) __nv_bfloat16 sA[2][BM * BK];
    __shared__ __align__(128) __nv_bfloat16 sB[2][BN * BK];

    const int tid = threadIdx.x;
    const int wid = tid >> 5, lid = tid & 31;
    const int wm = (wid & 1) * 64;        // warp m base (2 warps in m)
    const int wn = (wid >> 1) * 32;       // warp n base (4 warps in n)
    const int m0 = blockIdx.y * BM;
    const int n0 = blockIdx.x * BN;

    const uint32_t sa[2] = {smem_u32(&sA[0][0]), smem_u32(&sA[1][0])};
    const uint32_t sb[2] = {smem_u32(&sB[0][0]), smem_u32(&sB[1][0])};

    float acc[4][4][4];
#pragma unroll
    for (int i = 0; i < 4; i++)
#pragma unroll
        for (int j = 0; j < 4; j++)
#pragma unroll
            for (int q = 0; q < 4; q++) acc[i][j][q] = 0.f;

    // loader: chunk c (k32), stage s. 512 16B-chunks for A, 512 for B.
    auto load_chunk = [&](int c, int s) {
        const int seg = c / KSEG, kc = c % KSEG;
        const int acol = ((seg == 1) ? KK : 0) + kc * BK;
        const int bcol = ((seg == 2) ? KK : 0) + kc * BK;
        const __nv_bfloat16* ap = g_A2 + (size_t)m0 * K2 + acol;
        const __nv_bfloat16* bp = g_B2 + (size_t)n0 * K2 + bcol;
#pragma unroll
        for (int i = 0; i < 2; i++) {
            int q = tid + i * 256;
            int row = q >> 2, u = q & 3;
            CP16(sa[s] + swz(row, u), ap + (size_t)row * K2 + u * 8);
            CP16(sb[s] + swz(row, u), bp + (size_t)row * K2 + u * 8);
        }
        CP_COMMIT();
    };

    load_chunk(0, 0);

#pragma unroll 1
    for (int c = 0; c < NCHUNK; c++) {
        const int s = c & 1;
        if (c + 1 < NCHUNK) { load_chunk(c + 1, s ^ 1); CP_WAIT1(); }
        else                { CP_WAIT0(); }
        __syncthreads();

#pragma unroll
        for (int st = 0; st < 2; st++) {           // two k16 steps
            uint32_t af[4][4];
#pragma unroll
            for (int mf = 0; mf < 4; mf++) {
                int row = wm + mf * 16 + (lid & 15);
                int u = st * 2 + (lid >> 4);
                LDSM_X4(af[mf][0], af[mf][1], af[mf][2], af[mf][3], sa[s] + swz(row, u));
            }
            uint32_t bf[4][2];
#pragma unroll
            for (int p = 0; p < 2; p++) {          // n8-tile pairs
                int t = lid >> 3;
                int row = wn + (p * 2 + (t >> 1)) * 8 + (lid & 7);
                int u = st * 2 + (t & 1);
                LDSM_X4(bf[p * 2][0], bf[p * 2][1], bf[p * 2 + 1][0], bf[p * 2 + 1][1],
                        sb[s] + swz(row, u));
            }
#pragma unroll
            for (int mf = 0; mf < 4; mf++)
#pragma unroll
                for (int nf = 0; nf < 4; nf++)
                    MMA16816(acc[mf][nf], af[mf], bf[nf]);
        }
        __syncthreads();
    }

    // epilogue: c frag (row lid/4 [+8], col (lid%4)*2)
    const int mrow = m0 + wm + (lid >> 2);
    const int ncol = n0 + wn + (lid & 3) * 2;
#pragma unroll
    for (int mf = 0; mf < 4; mf++)
#pragma unroll
        for (int nf = 0; nf < 4; nf++) {
            float* p0 = g_y + (size_t)(mrow + mf * 16) * NNV + ncol + nf * 8;
            float* p1 = p0 + 8 * NNV;
            p0[0] = acc[mf][nf][0]; p0[1] = acc[mf][nf][1];
            p1[0] = acc[mf][nf][2]; p1[1] = acc[mf][nf][3];
        }
}

// ---------------- second contraction ----------------
__global__ void __launch_bounds__(256) transpose_wd(const float* __restrict__ Wd) {
    int idx = blockIdx.x * 256 + threadIdx.x;
    int c = idx >> 10, n = idx & 1023;
    g_wdt[idx] = Wd[(size_t)n * CC + c];
}

__global__ void __launch_bounds__(256) reduce_k(const float* __restrict__ Wb, float* __restrict__ out) {
    int idx = blockIdx.x * 256 + threadIdx.x;
    int b = idx >> 10, n = idx & 1023;
    const float* y = g_y + ((size_t)b * CC) * NNV + n;
    float s = 0.f;
#pragma unroll 8
    for (int c = 0; c < CC; c++)
        s = fmaf(y[(size_t)c * NNV], g_wdt[(size_t)c * NNV + n], s);
    out[idx] = s + Wb[n];
}

extern "C" void kernel_launch(void* const* d_in, const int* in_sizes, int n_in,
                              void* d_out, int out_size) {
    const float* x  = (const float*)d_in[0];   // (B, C, H, W)
    const float* Ws = (const float*)d_in[1];   // (N, H, W)
    const float* Wd = (const float*)d_in[2];   // (N, C, 1, 1)
    const float* Wb = (const float*)d_in[3];   // (1, N)
    float* out = (float*)d_out;                // (B, N)

    split_x<<<(MM * (KK / 4)) / 256, 256>>>(x);
    split_w<<<(NNV * (KK / 4)) / 256, 256>>>(Ws);
    transpose_wd<<<(CC * NNV) / 256, 256>>>(Wd);
    dim3 grid(NNV / BN, MM / BM);              // (8, 64)
    gemm_hmma<<<grid, 256>>>();
    reduce_k<<<(BB * NNV) / 256, 256>>>(Wb, out);
}